// round 7
// baseline (speedup 1.0000x reference)
#include <cuda_runtime.h>
#include <cuda_bf16.h>
#include <cstdint>
#include <cstddef>

#define BATCH 8
#define CCH   512
#define M2    1024          // 2*C rows of P
#define KDIM  4096
#define NTILES 8            // M2 / 128
#define NSTAGES 3
#define BLVL_BYTES 16384                 // one bf16 level image: 128 rows x 128B
#define BSTG_BYTES (3 * BLVL_BYTES)      // h,m,l (48KB)
#define NKB   (KDIM / 64)                // 64 k-blocks of 64 elems

// idesc kind::f16 (bf16): dtype F32 (1<<4) | atype BF16 (1<<7) | btype BF16 (1<<10)
//                       | (N/8)<<17 | (M/16)<<24
#define IDESC_BF16 0x08200490u

// Arch-specific ('a') feature gate: tcgen05 only exists in the sm_103a SASS pass.
#if defined(__CUDA_ARCH__) && (defined(__CUDA_ARCH_FEAT_SM103_ALL) || defined(__CUDA_ARCH_FEAT_SM100_ALL) || defined(__CUDA_ARCH_FEAT_SM101_ALL) || defined(__CUDA_ARCH_FEAT_SM110_ALL))
#define TC_OK 1
#else
#define TC_OK 0
#endif

// ---------------- scratch (static device globals; no allocation) ----------------
__device__ float          g_S[(size_t)BATCH * M2 * M2];   // 32 MB  S = P P^T
__device__ float          g_w[(size_t)BATCH * CCH * CCH];
__device__ unsigned short g_idx[(size_t)BATCH * CCH * CCH];
__device__ int            g_cnt[BATCH * CCH];

// ======================= helpers =======================
__device__ __forceinline__ uint32_t smem_u32(const void* p) {
    uint32_t a;
    asm("{ .reg .u64 t; cvta.to.shared.u64 t, %1; cvt.u32.u64 %0, t; }" : "=r"(a) : "l"(p));
    return a;
}

#if TC_OK
__device__ __forceinline__ void mbar_init(uint32_t a, uint32_t cnt) {
    asm volatile("mbarrier.init.shared.b64 [%0], %1;" :: "r"(a), "r"(cnt) : "memory");
}
__device__ __forceinline__ void mbar_inval(uint32_t a) {
    asm volatile("mbarrier.inval.shared.b64 [%0];" :: "r"(a) : "memory");
}
__device__ __forceinline__ void mbar_arrive(uint32_t a) {
    asm volatile("mbarrier.arrive.shared.b64 _, [%0];" :: "r"(a) : "memory");
}
__device__ __forceinline__ void mbar_wait(uint32_t a, uint32_t parity) {
    asm volatile(
        "{\n\t.reg .pred P;\n\t"
        "W%=:\n\t"
        "mbarrier.try_wait.parity.acquire.cta.shared::cta.b64 P, [%0], %1, 0x989680;\n\t"
        "@P bra.uni D%=;\n\t"
        "bra.uni W%=;\n\t"
        "D%=:\n\t}"
        :: "r"(a), "r"(parity) : "memory");
}
__device__ __forceinline__ uint64_t make_desc_sw128(uint32_t addr) {
    return ((uint64_t)2 << 61) | ((uint64_t)1 << 46) | ((uint64_t)64 << 32) |
           ((uint64_t)1 << 16) | (((uint64_t)(addr >> 4)) & 0x3FFF);
}
// TS-mode bf16 MMA: A from TMEM, B from SMEM descriptor
__device__ __forceinline__ void mma_bf16_ts(uint32_t d, uint32_t a_tmem, uint64_t bd, uint32_t en) {
    asm volatile(
        "{\n\t.reg .pred p;\n\t"
        "setp.ne.u32 p, %4, 0;\n\t"
        "tcgen05.mma.cta_group::1.kind::f16 [%0], [%1], %2, %3, {%5,%5,%5,%5}, p;\n\t}"
        :: "r"(d), "r"(a_tmem), "l"(bd), "r"(IDESC_BF16), "r"(en), "r"(0u) : "memory");
}
__device__ __forceinline__ void tc_commit(uint32_t mbar) {
    asm volatile(
        "tcgen05.commit.cta_group::1.mbarrier::arrive::one.shared::cluster.b64 [%0];"
        :: "r"(mbar) : "memory");
}
// 3-level bf16 split of a pair of fp32 (word = {lo: e0, hi: e1})
__device__ __forceinline__ void cvt3(float e0, float e1, uint32_t& hw, uint32_t& mw, uint32_t& lw) {
    asm("cvt.rn.bf16x2.f32 %0, %1, %2;" : "=r"(hw) : "f"(e1), "f"(e0));
    const float h0 = __uint_as_float(hw << 16), h1 = __uint_as_float(hw & 0xffff0000u);
    const float r0 = e0 - h0, r1 = e1 - h1;
    asm("cvt.rn.bf16x2.f32 %0, %1, %2;" : "=r"(mw) : "f"(r1), "f"(r0));
    const float m0 = __uint_as_float(mw << 16), m1 = __uint_as_float(mw & 0xffff0000u);
    const float s0 = r0 - m0, s1 = r1 - m1;
    asm("cvt.rn.bf16x2.f32 %0, %1, %2;" : "=r"(lw) : "f"(s1), "f"(s0));
}
__device__ __forceinline__ void sttm_x32(uint32_t tmem_addr, const uint32_t* r) {
    asm volatile(
        "tcgen05.st.sync.aligned.32x32b.x32.b32 [%0], "
        "{%1,%2,%3,%4,%5,%6,%7,%8,%9,%10,%11,%12,%13,%14,%15,%16,"
        "%17,%18,%19,%20,%21,%22,%23,%24,%25,%26,%27,%28,%29,%30,%31,%32};"
        :: "r"(tmem_addr),
           "r"(r[0]), "r"(r[1]), "r"(r[2]), "r"(r[3]), "r"(r[4]), "r"(r[5]), "r"(r[6]), "r"(r[7]),
           "r"(r[8]), "r"(r[9]), "r"(r[10]), "r"(r[11]), "r"(r[12]), "r"(r[13]), "r"(r[14]), "r"(r[15]),
           "r"(r[16]), "r"(r[17]), "r"(r[18]), "r"(r[19]), "r"(r[20]), "r"(r[21]), "r"(r[22]), "r"(r[23]),
           "r"(r[24]), "r"(r[25]), "r"(r[26]), "r"(r[27]), "r"(r[28]), "r"(r[29]), "r"(r[30]), "r"(r[31])
        : "memory");
}
#endif

// row-block base pointer in x (2,B,C,N): blocks of 128 rows, 512-boundary aligned
__device__ __forceinline__ const float* rowblk_base(const float* x, int b, int blk) {
    if (blk < 4) return x + ((size_t)b * CCH + blk * 128) * KDIM;
    return x + ((size_t)(BATCH + b) * CCH + (blk - 4) * 128) * KDIM;
}

// =======================================================================
// Kernel A: fused split+SYRK. TS-mode tcgen05 bf16 6-term, 128x128/CTA.
//   warps 0-3 (tid 0..127)   : A-group — LDG raw x, 3-level split, STTM
//   warps 4-7 (tid 128..255) : B-group — LDG raw x, split, swizzled STS
//   warp 8 lane 0 (tid 256)  : MMA issuer (24 dispatches/stage)
//   warps 0-3                : TMEM epilogue + mirror
// TMEM: D cols 0-127; A stage s at 128+s*96 (h/m/l at +0/+32/+64)
// =======================================================================
__global__ __launch_bounds__(288, 1) void syrk_tc_kernel(const float* __restrict__ x) {
#if TC_OK
    extern __shared__ char smem[];
    const uint32_t sb = smem_u32(smem);
    const uint32_t tb = (sb + 1023u) & ~1023u;            // 1024-aligned B tiles
    const uint32_t ctl = tb + NSTAGES * BSTG_BYTES;       // tmem ptr (16B)
    const uint32_t mb_ready = ctl + 16;                   // 3 x 8B, count 256
    const uint32_t mb_empty = ctl + 16 + 24;              // 3 x 8B, count 1 (commit)
    const uint32_t mb_done  = ctl + 16 + 48;

    const int tid = threadIdx.x;
    const int wid = tid >> 5, lid = tid & 31;

    const int b = blockIdx.y;
    int ti = 0, rem = blockIdx.x;
    while (rem >= NTILES - ti) { rem -= NTILES - ti; ti++; }
    const int tj = ti + rem;
    const bool diag = (ti == tj);

    if (wid == 0) {
        asm volatile("tcgen05.alloc.cta_group::1.sync.aligned.shared::cta.b32 [%0], %1;"
                     :: "r"(ctl), "r"(512u) : "memory");
    }
    if (tid == 0) {
        for (int s = 0; s < NSTAGES; s++) { mbar_init(mb_ready + s * 8, 256); mbar_init(mb_empty + s * 8, 1); }
        mbar_init(mb_done, 1);
        asm volatile("fence.proxy.async.shared::cta;" ::: "memory");
    }
    __syncthreads();

    uint32_t tmem;
    asm volatile("ld.shared.b32 %0, [%1];" : "=r"(tmem) : "r"(ctl));

    if (tid < 128) {
        // ================= A-group: thread = A row =================
        const float* pA = rowblk_base(x, b, ti) + (size_t)tid * KDIM;
        const uint32_t wo = (uint32_t)(wid << 21);
        int ph[NSTAGES] = {0, 0, 0};
        for (int kb = 0; kb < NKB; kb++) {
            const int s = kb % NSTAGES;
            // prefetch + convert in regs (no shared resources yet)
            uint32_t hv[32], mv[32], lv[32];
            const float4* p = (const float4*)(pA + (size_t)kb * 64);
            #pragma unroll
            for (int i = 0; i < 16; i++) {
                const float4 v = p[i];
                cvt3(v.x, v.y, hv[2 * i], mv[2 * i], lv[2 * i]);
                cvt3(v.z, v.w, hv[2 * i + 1], mv[2 * i + 1], lv[2 * i + 1]);
            }
            if (kb >= NSTAGES) { mbar_wait(mb_empty + s * 8, ph[s]); ph[s] ^= 1; }
            const uint32_t abase = tmem + 128 + s * 96 + wo;
            sttm_x32(abase,      hv);
            sttm_x32(abase + 32, mv);
            sttm_x32(abase + 64, lv);
            asm volatile("tcgen05.wait::st.sync.aligned;" ::: "memory");
            asm volatile("tcgen05.fence::before_thread_sync;" ::: "memory");
            mbar_arrive(mb_ready + s * 8);
        }
    } else if (tid < 256) {
        // ================= B-group: warp = 32 rows, lane = bf16x2 word =================
        const int wrp = wid - 4;                 // 0..3
        const float* pB0 = rowblk_base(x, b, tj) + (size_t)(wrp * 32) * KDIM + lid * 2;
        int ph[NSTAGES] = {0, 0, 0};
        for (int kb = 0; kb < NKB; kb++) {
            const int s = kb % NSTAGES;
            float2 ev[32];
            #pragma unroll
            for (int rr = 0; rr < 32; rr++)
                ev[rr] = *(const float2*)(pB0 + (size_t)rr * KDIM + (size_t)kb * 64);
            if (kb >= NSTAGES) { mbar_wait(mb_empty + s * 8, ph[s]); ph[s] ^= 1; }
            const uint32_t stg = tb + s * BSTG_BYTES;
            #pragma unroll
            for (int rr = 0; rr < 32; rr++) {
                uint32_t hw, mw, lw;
                cvt3(ev[rr].x, ev[rr].y, hw, mw, lw);
                const uint32_t off = (uint32_t)((wrp * 32 + rr) * 128 + lid * 4);
                const uint32_t sw = off ^ ((off >> 3) & 0x70u);
                const uint32_t a0 = stg + sw;
                asm volatile("st.shared.b32 [%0], %1;" :: "r"(a0), "r"(hw) : "memory");
                asm volatile("st.shared.b32 [%0], %1;" :: "r"(a0 + BLVL_BYTES), "r"(mw) : "memory");
                asm volatile("st.shared.b32 [%0], %1;" :: "r"(a0 + 2 * BLVL_BYTES), "r"(lw) : "memory");
            }
            asm volatile("fence.proxy.async.shared::cta;" ::: "memory");
            mbar_arrive(mb_ready + s * 8);
        }
    } else if (tid == 256) {
        // ================= MMA issuer =================
        int ph[NSTAGES] = {0, 0, 0};
        uint32_t en = 0;
        for (int kb = 0; kb < NKB; kb++) {
            const int s = kb % NSTAGES;
            mbar_wait(mb_ready + s * 8, ph[s]); ph[s] ^= 1;
            asm volatile("tcgen05.fence::after_thread_sync;" ::: "memory");
            const uint32_t stg = tb + s * BSTG_BYTES;
            const uint64_t dBh = make_desc_sw128(stg);
            const uint64_t dBm = make_desc_sw128(stg + BLVL_BYTES);
            const uint64_t dBl = make_desc_sw128(stg + 2 * BLVL_BYTES);
            const uint32_t aS = tmem + 128 + s * 96;
            #pragma unroll
            for (int k = 0; k < 4; k++) {        // 4 k-steps of 16 bf16
                const uint64_t o = k * 2;
                const uint32_t ah = aS + k * 8, am = aS + 32 + k * 8, al = aS + 64 + k * 8;
                mma_bf16_ts(tmem, ah, dBh + o, en); en = 1;
                mma_bf16_ts(tmem, ah, dBm + o, 1);
                mma_bf16_ts(tmem, am, dBh + o, 1);
                mma_bf16_ts(tmem, am, dBm + o, 1);
                mma_bf16_ts(tmem, ah, dBl + o, 1);
                mma_bf16_ts(tmem, al, dBh + o, 1);
            }
            tc_commit(mb_empty + s * 8);
        }
        tc_commit(mb_done);
    }

    // ---------------- epilogue ----------------
    mbar_wait(mb_done, 0);
    asm volatile("tcgen05.fence::after_thread_sync;" ::: "memory");

    const size_t Sb = (size_t)b * M2 * M2;
    const int r0 = ti * 128, c0 = tj * 128;

    if (wid < 4) {
        const int row = r0 + wid * 32 + lid;
        for (int cb = 0; cb < 4; cb++) {
            uint32_t d[32];
            asm volatile(
                "tcgen05.ld.sync.aligned.32x32b.x32.b32 "
                "{%0,%1,%2,%3,%4,%5,%6,%7,%8,%9,%10,%11,%12,%13,%14,%15,"
                "%16,%17,%18,%19,%20,%21,%22,%23,%24,%25,%26,%27,%28,%29,%30,%31}, [%32];"
                : "=r"(d[0]), "=r"(d[1]), "=r"(d[2]), "=r"(d[3]), "=r"(d[4]), "=r"(d[5]), "=r"(d[6]), "=r"(d[7]),
                  "=r"(d[8]), "=r"(d[9]), "=r"(d[10]), "=r"(d[11]), "=r"(d[12]), "=r"(d[13]), "=r"(d[14]), "=r"(d[15]),
                  "=r"(d[16]), "=r"(d[17]), "=r"(d[18]), "=r"(d[19]), "=r"(d[20]), "=r"(d[21]), "=r"(d[22]), "=r"(d[23]),
                  "=r"(d[24]), "=r"(d[25]), "=r"(d[26]), "=r"(d[27]), "=r"(d[28]), "=r"(d[29]), "=r"(d[30]), "=r"(d[31])
                : "r"(tmem + cb * 32));
            asm volatile("tcgen05.wait::ld.sync.aligned;" ::: "memory");

            float* dst = g_S + Sb + (size_t)row * M2 + c0 + cb * 32;
            #pragma unroll
            for (int q = 0; q < 8; q++) {
                float4 v = make_float4(__uint_as_float(d[q * 4 + 0]), __uint_as_float(d[q * 4 + 1]),
                                       __uint_as_float(d[q * 4 + 2]), __uint_as_float(d[q * 4 + 3]));
                *(float4*)(dst + q * 4) = v;
            }
            if (!diag) {
                #pragma unroll
                for (int j = 0; j < 32; j++)
                    g_S[Sb + (size_t)(c0 + cb * 32 + j) * M2 + row] = __uint_as_float(d[j]);
            }
        }
    }

    __syncthreads();
    if (tid == 0) {
        for (int s = 0; s < NSTAGES; s++) { mbar_inval(mb_ready + s * 8); mbar_inval(mb_empty + s * 8); }
        mbar_inval(mb_done);
    }
    __syncthreads();
    if (wid == 0) {
        asm volatile("tcgen05.dealloc.cta_group::1.sync.aligned.b32 %0, %1;" :: "r"(tmem), "r"(512u));
    }
#endif
}

// =======================================================================
// Kernel B: softmax of (max-er)^2+(max-ei)^2 over S rows + compaction
// =======================================================================
__device__ __forceinline__ float blkReduce(float v, float* red, bool isMax) {
    #pragma unroll
    for (int o = 16; o > 0; o >>= 1) {
        float tv = __shfl_xor_sync(0xffffffffu, v, o);
        v = isMax ? fmaxf(v, tv) : (v + tv);
    }
    const int lane = threadIdx.x & 31, wid = threadIdx.x >> 5;
    if (lane == 0) red[wid] = v;
    __syncthreads();
    if (wid == 0) {
        float tv = (lane < 16) ? red[lane] : (isMax ? -3.4e38f : 0.0f);
        #pragma unroll
        for (int o = 8; o > 0; o >>= 1) {
            float u = __shfl_xor_sync(0xffffffffu, tv, o);
            tv = isMax ? fmaxf(tv, u) : (tv + u);
        }
        if (lane == 0) red[0] = tv;
    }
    __syncthreads();
    const float res = red[0];
    __syncthreads();
    return res;
}

__global__ void attn_kernel() {
    __shared__ float red[16];
    __shared__ int wcnt[16];
    __shared__ int woff[16];

    const int r = blockIdx.x;
    const int b = r >> 9, c = r & 511;
    const int d = threadIdx.x;
    const int lane = d & 31, wid = d >> 5;

    const float* S0 = g_S + ((size_t)b * M2 + c) * M2;
    const float* S1 = g_S + ((size_t)b * M2 + CCH + c) * M2;

    const float er = S0[d] - S1[CCH + d];
    const float ei = S0[CCH + d] + S1[d];

    const float mer = blkReduce(er, red, true);
    const float mei = blkReduce(ei, red, true);

    const float ar = mer - er;
    const float ai = mei - ei;
    const float s = ar * ar + ai * ai;

    const float smax = blkReduce(s, red, true);
    const float e = expf(s - smax);
    const float Z = blkReduce(e, red, false);
    const float w = e / Z;

    const bool keep = w > 1e-10f;
    const unsigned msk = __ballot_sync(0xffffffffu, keep);
    const int inpos = __popc(msk & ((1u << lane) - 1u));
    if (lane == 0) wcnt[wid] = __popc(msk);
    __syncthreads();
    if (d == 0) {
        int run = 0;
        #pragma unroll
        for (int i = 0; i < 16; i++) { woff[i] = run; run += wcnt[i]; }
        g_cnt[r] = run;
    }
    __syncthreads();
    if (keep) {
        const int pos = woff[wid] + inpos;
        g_idx[(size_t)r * CCH + pos] = (unsigned short)d;
        g_w[(size_t)r * CCH + pos] = w;
    }
}

// =======================================================================
// Kernel C: out = gamma * (sparse attention @ q) + x
// =======================================================================
__global__ __launch_bounds__(256) void apply_kernel(const float* __restrict__ x,
                                                    const float* __restrict__ gamma,
                                                    float* __restrict__ out) {
    const int r = blockIdx.x;
    const int b = r >> 9, c = r & 511;
    const int n = blockIdx.y * 1024 + threadIdx.x * 4;

    const int cnt = g_cnt[r];
    const float g = gamma[0];
    const size_t imagOff = (size_t)BATCH * CCH * KDIM;
    const float* xr = x;
    const float* xi = x + imagOff;

    float4 ar = make_float4(0.f, 0.f, 0.f, 0.f);
    float4 ai = make_float4(0.f, 0.f, 0.f, 0.f);
    const size_t lbase = (size_t)r * CCH;

    for (int i = 0; i < cnt; i++) {
        const int dch = g_idx[lbase + i];
        const float w = g_w[lbase + i];
        const size_t q = ((size_t)b * CCH + dch) * KDIM + n;
        const float4 qr = *(const float4*)(xr + q);
        const float4 qi = *(const float4*)(xi + q);
        ar.x += w * qr.x; ar.y += w * qr.y; ar.z += w * qr.z; ar.w += w * qr.w;
        ai.x += w * qi.x; ai.y += w * qi.y; ai.z += w * qi.z; ai.w += w * qi.w;
    }

    const size_t o = ((size_t)b * CCH + c) * KDIM + n;
    const float4 xrv = *(const float4*)(xr + o);
    const float4 xiv = *(const float4*)(xi + o);
    float4 orr = make_float4(g * ar.x + xrv.x, g * ar.y + xrv.y,
                             g * ar.z + xrv.z, g * ar.w + xrv.w);
    float4 oii = make_float4(g * ai.x + xiv.x, g * ai.y + xiv.y,
                             g * ai.z + xiv.z, g * ai.w + xiv.w);
    *(float4*)(out + o) = orr;
    *(float4*)(out + imagOff + o) = oii;
}

// =======================================================================
extern "C" void kernel_launch(void* const* d_in, const int* in_sizes, int n_in,
                              void* d_out, int out_size) {
    const float* x = (const float*)d_in[0];
    const float* gamma = (const float*)d_in[1];
    float* out = (float*)d_out;

    const int SMEM_DYN = 1024 + NSTAGES * BSTG_BYTES + 256;   // ~145 KB
    cudaFuncSetAttribute(syrk_tc_kernel, cudaFuncAttributeMaxDynamicSharedMemorySize, SMEM_DYN);

    syrk_tc_kernel<<<dim3(NTILES * (NTILES + 1) / 2, BATCH), 288, SMEM_DYN>>>(x);
    attn_kernel<<<BATCH * CCH, 512>>>();
    apply_kernel<<<dim3(BATCH * CCH, 4), 256>>>(x, gamma, out);
}

// round 8
// speedup vs baseline: 1.3191x; 1.3191x over previous
#include <cuda_runtime.h>
#include <cuda_bf16.h>
#include <cstdint>
#include <cstddef>

#define BATCH 8
#define CCH   512
#define M2    1024          // 2*C rows of P
#define KDIM  4096
#define NTILES 8            // M2 / 128
#define NSTAGES 2
#define TILE_BYTES (128 * 128)          // 16KB: 128 rows x 128B (64 bf16), SW128 image
#define OPER_BYTES (3 * TILE_BYTES)     // h, m, l images packed contiguously (48KB)
#define STAGE_BYTES (2 * OPER_BYTES)    // A block + B block (96KB)
#define NKB   (KDIM / 64)               // 64 k-blocks of 64 bf16

// idesc kind::f16 (bf16 in): dtype F32 (1<<4) | atype BF16 (1<<7) | btype BF16 (1<<10)
//                          | (N/8)<<17 | (M/16)<<24, K-major both sides
#define IDESC_BF16 0x08200490u

// Arch-specific ('a') feature gate: tcgen05 only exists in the sm_103a SASS pass.
#if defined(__CUDA_ARCH__) && (defined(__CUDA_ARCH_FEAT_SM103_ALL) || defined(__CUDA_ARCH_FEAT_SM100_ALL) || defined(__CUDA_ARCH_FEAT_SM101_ALL) || defined(__CUDA_ARCH_FEAT_SM110_ALL))
#define TC_OK 1
#else
#define TC_OK 0
#endif

// ---------------- scratch (static device globals; no allocation) ----------------
// packed 3-level bf16 images: [b][rowblk(8)][kb(64)] -> 48KB block {h,m,l} of
// 128 rows x 64 bf16, each 16KB SW128-swizzled
__device__ uint32_t       g_pack[(size_t)BATCH * 8 * NKB * 12288];  // 192 MB
__device__ float          g_S[(size_t)BATCH * M2 * M2];             // 32 MB  S = P P^T
__device__ float          g_w[(size_t)BATCH * CCH * CCH];
__device__ unsigned short g_idx[(size_t)BATCH * CCH * CCH];
__device__ int            g_cnt[BATCH * CCH];

// ======================= helpers =======================
__device__ __forceinline__ uint32_t smem_u32(const void* p) {
    uint32_t a;
    asm("{ .reg .u64 t; cvta.to.shared.u64 t, %1; cvt.u32.u64 %0, t; }" : "=r"(a) : "l"(p));
    return a;
}

// 3-level bf16 split of a pair of fp32 -> packed bf16x2 words (elem0 in low half)
__device__ __forceinline__ void cvt3p(float e0, float e1, uint32_t& hw, uint32_t& mw, uint32_t& lw) {
    asm("cvt.rn.bf16x2.f32 %0, %1, %2;" : "=r"(hw) : "f"(e1), "f"(e0));
    const float h0 = __uint_as_float(hw << 16), h1 = __uint_as_float(hw & 0xffff0000u);
    const float r0 = e0 - h0, r1 = e1 - h1;
    asm("cvt.rn.bf16x2.f32 %0, %1, %2;" : "=r"(mw) : "f"(r1), "f"(r0));
    const float m0 = __uint_as_float(mw << 16), m1 = __uint_as_float(mw & 0xffff0000u);
    const float s0 = r0 - m0, s1 = r1 - m1;
    asm("cvt.rn.bf16x2.f32 %0, %1, %2;" : "=r"(lw) : "f"(s1), "f"(s0));
}

// =======================================================================
// Kernel 0: split fp32 -> 3 bf16 levels (h, m, l), written pre-tiled and
// pre-SW128-swizzled into contiguous 48KB {h,m,l} blocks per (rowblk, kb).
// Each thread: 8 consecutive elements -> 3 x 16B swizzled stores.
// =======================================================================
__global__ __launch_bounds__(256) void split_kernel(const float* __restrict__ x) {
    const size_t idx = (size_t)blockIdx.x * 256 + threadIdx.x;   // 8*1024*512 groups
    const int b   = (int)(idx >> 19);
    const int row = (int)((idx >> 9) & 1023);
    const int k8  = (int)(idx & 511);                            // group of 8 elems

    size_t src;
    if (row < CCH) src = ((size_t)b * CCH + row) * KDIM + (size_t)k8 * 8;
    else           src = ((size_t)(BATCH + b) * CCH + (row - CCH)) * KDIM + (size_t)k8 * 8;

    const float4 v0 = *(const float4*)(x + src);
    const float4 v1 = *(const float4*)(x + src + 4);

    uint4 hv, mv, lv;
    cvt3p(v0.x, v0.y, hv.x, mv.x, lv.x);
    cvt3p(v0.z, v0.w, hv.y, mv.y, lv.y);
    cvt3p(v1.x, v1.y, hv.z, mv.z, lv.z);
    cvt3p(v1.z, v1.w, hv.w, mv.w, lv.w);

    const int rb = row >> 7, r = row & 127;
    const int kb = k8 >> 3;                               // 64 kbs of 64 elems
    const uint32_t byte_off = (uint32_t)r * 128u + (uint32_t)(k8 & 7) * 16u;
    const uint32_t sw = byte_off ^ ((byte_off >> 3) & 0x70u);
    char* base = (char*)g_pack + ((((size_t)b * 8 + rb) * NKB) + kb) * 49152 + sw;

    *(uint4*)(base)                  = hv;
    *(uint4*)(base + TILE_BYTES)     = mv;
    *(uint4*)(base + 2 * TILE_BYTES) = lv;
}

// =======================================================================
// Kernel A: tcgen05 bf16 6-term SYRK, 128x128 tile per CTA, 128 threads.
//   thread 0  : bulk-copy producer (sub-stage: h first, then m+l)
//   thread 32 : MMA issuer (hh overlapped with m/l fill)
//   warps 0-3 : TMEM epilogue, mirror via smem transpose
// =======================================================================
#if TC_OK
__device__ __forceinline__ void mbar_init(uint32_t a, uint32_t cnt) {
    asm volatile("mbarrier.init.shared.b64 [%0], %1;" :: "r"(a), "r"(cnt) : "memory");
}
__device__ __forceinline__ void mbar_inval(uint32_t a) {
    asm volatile("mbarrier.inval.shared.b64 [%0];" :: "r"(a) : "memory");
}
__device__ __forceinline__ void mbar_expect_tx(uint32_t a, uint32_t bytes) {
    asm volatile("mbarrier.arrive.expect_tx.shared.b64 _, [%0], %1;" :: "r"(a), "r"(bytes) : "memory");
}
__device__ __forceinline__ void mbar_wait(uint32_t a, uint32_t parity) {
    asm volatile(
        "{\n\t.reg .pred P;\n\t"
        "W%=:\n\t"
        "mbarrier.try_wait.parity.acquire.cta.shared::cta.b64 P, [%0], %1, 0x989680;\n\t"
        "@P bra.uni D%=;\n\t"
        "bra.uni W%=;\n\t"
        "D%=:\n\t}"
        :: "r"(a), "r"(parity) : "memory");
}
__device__ __forceinline__ void bulk_g2s(uint32_t dst, const void* src, uint32_t bytes, uint32_t mbar) {
    asm volatile(
        "cp.async.bulk.shared::cta.global.mbarrier::complete_tx::bytes [%0], [%1], %2, [%3];"
        :: "r"(dst), "l"(src), "r"(bytes), "r"(mbar) : "memory");
}
__device__ __forceinline__ uint64_t make_desc_sw128(uint32_t addr) {
    return ((uint64_t)2 << 61) | ((uint64_t)1 << 46) | ((uint64_t)64 << 32) |
           ((uint64_t)1 << 16) | (((uint64_t)(addr >> 4)) & 0x3FFF);
}
__device__ __forceinline__ void mma_bf16_ss(uint32_t d, uint64_t ad, uint64_t bd, uint32_t en) {
    asm volatile(
        "{\n\t.reg .pred p;\n\t"
        "setp.ne.u32 p, %4, 0;\n\t"
        "tcgen05.mma.cta_group::1.kind::f16 [%0], %1, %2, %3, {%5,%5,%5,%5}, p;\n\t}"
        :: "r"(d), "l"(ad), "l"(bd), "r"(IDESC_BF16), "r"(en), "r"(0u) : "memory");
}
__device__ __forceinline__ void tc_commit(uint32_t mbar) {
    asm volatile(
        "tcgen05.commit.cta_group::1.mbarrier::arrive::one.shared::cluster.b64 [%0];"
        :: "r"(mbar) : "memory");
}
#endif

__global__ __launch_bounds__(128, 1) void syrk_tc_kernel() {
#if TC_OK
    extern __shared__ char smem[];
    const uint32_t sb = smem_u32(smem);
    const uint32_t tb = (sb + 1023u) & ~1023u;            // 1024-aligned tile base
    const uint32_t ctl = tb + NSTAGES * STAGE_BYTES;      // control area
    const uint32_t mb_full1 = ctl + 16;                   // 2 x 8B (h images landed)
    const uint32_t mb_full2 = ctl + 16 + 16;              // 2 x 8B (m+l landed)
    const uint32_t mb_empty = ctl + 16 + 32;              // 2 x 8B
    const uint32_t mb_done  = ctl + 16 + 48;

    const int tid = threadIdx.x;
    const int wid = tid >> 5, lid = tid & 31;

    const int b = blockIdx.y;
    int ti = 0, rem = blockIdx.x;
    while (rem >= NTILES - ti) { rem -= NTILES - ti; ti++; }
    const int tj = ti + rem;
    const bool diag = (ti == tj);

    if (wid == 0) {
        asm volatile("tcgen05.alloc.cta_group::1.sync.aligned.shared::cta.b32 [%0], %1;"
                     :: "r"(ctl), "r"(128u) : "memory");
    }
    if (tid == 0) {
        for (int s = 0; s < NSTAGES; s++) {
            mbar_init(mb_full1 + s * 8, 1); mbar_init(mb_full2 + s * 8, 1);
            mbar_init(mb_empty + s * 8, 1);
        }
        mbar_init(mb_done, 1);
        asm volatile("fence.proxy.async.shared::cta;" ::: "memory");
    }
    __syncthreads();

    uint32_t tmem;
    asm volatile("ld.shared.b32 %0, [%1];" : "=r"(tmem) : "r"(ctl));

    const uint32_t tx1 = diag ? TILE_BYTES : (2 * TILE_BYTES);          // h images
    const uint32_t tx2 = diag ? (2 * TILE_BYTES) : (4 * TILE_BYTES);    // m+l images

    if (tid == 0) {
        // ---------------- producer: h first, then m+l ----------------
        const char* tiA = (const char*)g_pack + (((size_t)b * 8 + ti) * NKB) * 49152;
        const char* tiB = (const char*)g_pack + (((size_t)b * 8 + tj) * NKB) * 49152;
        int ph[NSTAGES] = {0, 0};
        for (int kb = 0; kb < NKB; kb++) {
            const int s = kb & 1;
            if (kb >= NSTAGES) { mbar_wait(mb_empty + s * 8, ph[s]); ph[s] ^= 1; }
            const uint32_t st = tb + s * STAGE_BYTES;
            const uint32_t fb1 = mb_full1 + s * 8;
            const uint32_t fb2 = mb_full2 + s * 8;
            const char* srcA = tiA + (size_t)kb * 49152;
            const char* srcB = tiB + (size_t)kb * 49152;
            mbar_expect_tx(fb1, tx1);
            bulk_g2s(st, srcA, TILE_BYTES, fb1);                               // A.h
            if (!diag) bulk_g2s(st + OPER_BYTES, srcB, TILE_BYTES, fb1);       // B.h
            mbar_expect_tx(fb2, tx2);
            bulk_g2s(st + TILE_BYTES, srcA + TILE_BYTES, 2 * TILE_BYTES, fb2); // A.m+A.l
            if (!diag)
                bulk_g2s(st + OPER_BYTES + TILE_BYTES, srcB + TILE_BYTES, 2 * TILE_BYTES, fb2);
        }
    } else if (tid == 32) {
        // ---------------- MMA issuer ----------------
        int ph1[NSTAGES] = {0, 0}, ph2[NSTAGES] = {0, 0};
        uint32_t en = 0;
        for (int kb = 0; kb < NKB; kb++) {
            const int s = kb & 1;
            const uint32_t st = tb + s * STAGE_BYTES;
            const uint64_t dAh = make_desc_sw128(st);
            const uint64_t dAm = make_desc_sw128(st + TILE_BYTES);
            const uint64_t dAl = make_desc_sw128(st + 2 * TILE_BYTES);
            const uint64_t dBh = diag ? dAh : make_desc_sw128(st + OPER_BYTES);
            const uint64_t dBm = diag ? dAm : make_desc_sw128(st + OPER_BYTES + TILE_BYTES);
            const uint64_t dBl = diag ? dAl : make_desc_sw128(st + OPER_BYTES + 2 * TILE_BYTES);

            mbar_wait(mb_full1 + s * 8, ph1[s]); ph1[s] ^= 1;
            #pragma unroll
            for (int k = 0; k < 4; k++) {        // hh as soon as h lands
                mma_bf16_ss(tmem, dAh + k * 2, dBh + k * 2, en); en = 1;
            }
            mbar_wait(mb_full2 + s * 8, ph2[s]); ph2[s] ^= 1;
            #pragma unroll
            for (int k = 0; k < 4; k++) {        // remaining 5 terms
                const uint64_t o = k * 2;
                mma_bf16_ss(tmem, dAh + o, dBm + o, 1);
                mma_bf16_ss(tmem, dAm + o, dBh + o, 1);
                mma_bf16_ss(tmem, dAm + o, dBm + o, 1);
                mma_bf16_ss(tmem, dAh + o, dBl + o, 1);
                mma_bf16_ss(tmem, dAl + o, dBh + o, 1);
            }
            tc_commit(mb_empty + s * 8);
        }
        tc_commit(mb_done);
    }

    // ---------------- epilogue ----------------
    mbar_wait(mb_done, 0);
    asm volatile("tcgen05.fence::after_thread_sync;" ::: "memory");

    const size_t Sb = (size_t)b * M2 * M2;
    const int r0 = ti * 128, c0 = tj * 128;
    const int row = r0 + wid * 32 + lid;
    float* trsp = (float*)(smem + (tb - sb));            // reuse stage buffers (32x132 floats)

    for (int cb = 0; cb < 4; cb++) {
        uint32_t d[32];
        asm volatile(
            "tcgen05.ld.sync.aligned.32x32b.x32.b32 "
            "{%0,%1,%2,%3,%4,%5,%6,%7,%8,%9,%10,%11,%12,%13,%14,%15,"
            "%16,%17,%18,%19,%20,%21,%22,%23,%24,%25,%26,%27,%28,%29,%30,%31}, [%32];"
            : "=r"(d[0]), "=r"(d[1]), "=r"(d[2]), "=r"(d[3]), "=r"(d[4]), "=r"(d[5]), "=r"(d[6]), "=r"(d[7]),
              "=r"(d[8]), "=r"(d[9]), "=r"(d[10]), "=r"(d[11]), "=r"(d[12]), "=r"(d[13]), "=r"(d[14]), "=r"(d[15]),
              "=r"(d[16]), "=r"(d[17]), "=r"(d[18]), "=r"(d[19]), "=r"(d[20]), "=r"(d[21]), "=r"(d[22]), "=r"(d[23]),
              "=r"(d[24]), "=r"(d[25]), "=r"(d[26]), "=r"(d[27]), "=r"(d[28]), "=r"(d[29]), "=r"(d[30]), "=r"(d[31])
            : "r"(tmem + cb * 32));
        asm volatile("tcgen05.wait::ld.sync.aligned;" ::: "memory");

        float* dst = g_S + Sb + (size_t)row * M2 + c0 + cb * 32;
        #pragma unroll
        for (int q = 0; q < 8; q++) {
            float4 v = make_float4(__uint_as_float(d[q * 4 + 0]), __uint_as_float(d[q * 4 + 1]),
                                   __uint_as_float(d[q * 4 + 2]), __uint_as_float(d[q * 4 + 3]));
            *(float4*)(dst + q * 4) = v;
        }

        if (!diag) {
            // transpose 128x32 -> 32x128 via smem, then coalesced STG
            const int lr = wid * 32 + lid;       // local row 0..127
            #pragma unroll
            for (int j = 0; j < 32; j++)
                trsp[j * 132 + lr] = __uint_as_float(d[j]);
            __syncthreads();
            const int mj = tid >> 2;             // mirror row 0..31 (local)
            const int ch = tid & 3;              // 32-col chunk
            float* mdst = g_S + Sb + (size_t)(c0 + cb * 32 + mj) * M2 + r0 + ch * 32;
            const float* msrc = trsp + mj * 132 + ch * 32;
            #pragma unroll
            for (int q = 0; q < 8; q++)
                *(float4*)(mdst + q * 4) = *(const float4*)(msrc + q * 4);
            __syncthreads();
        }
    }

    __syncthreads();
    if (tid == 0) {
        for (int s = 0; s < NSTAGES; s++) {
            mbar_inval(mb_full1 + s * 8); mbar_inval(mb_full2 + s * 8); mbar_inval(mb_empty + s * 8);
        }
        mbar_inval(mb_done);
    }
    __syncthreads();
    if (wid == 0) {
        asm volatile("tcgen05.dealloc.cta_group::1.sync.aligned.b32 %0, %1;" :: "r"(tmem), "r"(128u));
    }
#endif
}

// =======================================================================
// Kernel B: softmax of (max-er)^2+(max-ei)^2 over S rows + compaction
// =======================================================================
__device__ __forceinline__ float blkReduce(float v, float* red, bool isMax) {
    #pragma unroll
    for (int o = 16; o > 0; o >>= 1) {
        float tv = __shfl_xor_sync(0xffffffffu, v, o);
        v = isMax ? fmaxf(v, tv) : (v + tv);
    }
    const int lane = threadIdx.x & 31, wid = threadIdx.x >> 5;
    if (lane == 0) red[wid] = v;
    __syncthreads();
    if (wid == 0) {
        float tv = (lane < 16) ? red[lane] : (isMax ? -3.4e38f : 0.0f);
        #pragma unroll
        for (int o = 8; o > 0; o >>= 1) {
            float u = __shfl_xor_sync(0xffffffffu, tv, o);
            tv = isMax ? fmaxf(tv, u) : (tv + u);
        }
        if (lane == 0) red[0] = tv;
    }
    __syncthreads();
    const float res = red[0];
    __syncthreads();
    return res;
}

__global__ void attn_kernel() {
    __shared__ float red[16];
    __shared__ int wcnt[16];
    __shared__ int woff[16];

    const int r = blockIdx.x;
    const int b = r >> 9, c = r & 511;
    const int d = threadIdx.x;
    const int lane = d & 31, wid = d >> 5;

    const float* S0 = g_S + ((size_t)b * M2 + c) * M2;
    const float* S1 = g_S + ((size_t)b * M2 + CCH + c) * M2;

    const float er = S0[d] - S1[CCH + d];
    const float ei = S0[CCH + d] + S1[d];

    const float mer = blkReduce(er, red, true);
    const float mei = blkReduce(ei, red, true);

    const float ar = mer - er;
    const float ai = mei - ei;
    const float s = ar * ar + ai * ai;

    const float smax = blkReduce(s, red, true);
    const float e = expf(s - smax);
    const float Z = blkReduce(e, red, false);
    const float w = e / Z;

    const bool keep = w > 1e-10f;
    const unsigned msk = __ballot_sync(0xffffffffu, keep);
    const int inpos = __popc(msk & ((1u << lane) - 1u));
    if (lane == 0) wcnt[wid] = __popc(msk);
    __syncthreads();
    if (d == 0) {
        int run = 0;
        #pragma unroll
        for (int i = 0; i < 16; i++) { woff[i] = run; run += wcnt[i]; }
        g_cnt[r] = run;
    }
    __syncthreads();
    if (keep) {
        const int pos = woff[wid] + inpos;
        g_idx[(size_t)r * CCH + pos] = (unsigned short)d;
        g_w[(size_t)r * CCH + pos] = w;
    }
}

// =======================================================================
// Kernel C: out = gamma * (sparse attention @ q) + x  (2 float4 per thread)
// =======================================================================
__global__ __launch_bounds__(256) void apply_kernel(const float* __restrict__ x,
                                                    const float* __restrict__ gamma,
                                                    float* __restrict__ out) {
    const int r = blockIdx.x;
    const int b = r >> 9, c = r & 511;
    const int n = blockIdx.y * 2048 + threadIdx.x * 4;   // covers n and n+1024

    const int cnt = g_cnt[r];
    const float g = gamma[0];
    const size_t imagOff = (size_t)BATCH * CCH * KDIM;
    const float* xr = x;
    const float* xi = x + imagOff;

    float4 ar0 = make_float4(0.f, 0.f, 0.f, 0.f), ar1 = ar0;
    float4 ai0 = ar0, ai1 = ar0;
    const size_t lbase = (size_t)r * CCH;

    for (int i = 0; i < cnt; i++) {
        const int dch = g_idx[lbase + i];
        const float w = g_w[lbase + i];
        const size_t q = ((size_t)b * CCH + dch) * KDIM + n;
        const float4 qr0 = *(const float4*)(xr + q);
        const float4 qr1 = *(const float4*)(xr + q + 1024);
        const float4 qi0 = *(const float4*)(xi + q);
        const float4 qi1 = *(const float4*)(xi + q + 1024);
        ar0.x += w * qr0.x; ar0.y += w * qr0.y; ar0.z += w * qr0.z; ar0.w += w * qr0.w;
        ar1.x += w * qr1.x; ar1.y += w * qr1.y; ar1.z += w * qr1.z; ar1.w += w * qr1.w;
        ai0.x += w * qi0.x; ai0.y += w * qi0.y; ai0.z += w * qi0.z; ai0.w += w * qi0.w;
        ai1.x += w * qi1.x; ai1.y += w * qi1.y; ai1.z += w * qi1.z; ai1.w += w * qi1.w;
    }

    const size_t o = ((size_t)b * CCH + c) * KDIM + n;
    {
        const float4 xv = *(const float4*)(xr + o);
        *(float4*)(out + o) = make_float4(g * ar0.x + xv.x, g * ar0.y + xv.y,
                                          g * ar0.z + xv.z, g * ar0.w + xv.w);
    }
    {
        const float4 xv = *(const float4*)(xr + o + 1024);
        *(float4*)(out + o + 1024) = make_float4(g * ar1.x + xv.x, g * ar1.y + xv.y,
                                                 g * ar1.z + xv.z, g * ar1.w + xv.w);
    }
    {
        const float4 xv = *(const float4*)(xi + o);
        *(float4*)(out + imagOff + o) = make_float4(g * ai0.x + xv.x, g * ai0.y + xv.y,
                                                    g * ai0.z + xv.z, g * ai0.w + xv.w);
    }
    {
        const float4 xv = *(const float4*)(xi + o + 1024);
        *(float4*)(out + imagOff + o + 1024) = make_float4(g * ai1.x + xv.x, g * ai1.y + xv.y,
                                                           g * ai1.z + xv.z, g * ai1.w + xv.w);
    }
}

// =======================================================================
extern "C" void kernel_launch(void* const* d_in, const int* in_sizes, int n_in,
                              void* d_out, int out_size) {
    const float* x = (const float*)d_in[0];
    const float* gamma = (const float*)d_in[1];
    float* out = (float*)d_out;

    const int SMEM_DYN = 1024 + NSTAGES * STAGE_BYTES + 256;   // ~193.5 KB
    cudaFuncSetAttribute(syrk_tc_kernel, cudaFuncAttributeMaxDynamicSharedMemorySize, SMEM_DYN);

    split_kernel<<<(BATCH * 1024 * 512) / 256, 256>>>(x);
    syrk_tc_kernel<<<dim3(NTILES * (NTILES + 1) / 2, BATCH), 128, SMEM_DYN>>>();
    attn_kernel<<<BATCH * CCH, 512>>>();
    apply_kernel<<<dim3(BATCH * CCH, 2), 256>>>(x, gamma, out);
}

// round 9
// speedup vs baseline: 1.5254x; 1.1564x over previous
#include <cuda_runtime.h>
#include <cuda_fp16.h>
#include <cstdint>
#include <cstddef>

#define BATCH 8
#define CCH   512
#define M2    1024          // 2*C rows of P
#define KDIM  4096
#define NTILES 8            // M2 / 128
#define NSTAGES 3
#define IMG_BYTES 16384                 // one fp16 level image: 128 rows x 128B (64 fp16)
#define OPER_BYTES (2 * IMG_BYTES)      // h, m images packed contiguously (32KB)
#define STAGE_BYTES (2 * OPER_BYTES)    // A block + B block (64KB)
#define NKB   (KDIM / 64)               // 64 k-blocks of 64 elems

// idesc kind::f16 (fp16 in): dtype F32 (1<<4) | atype FP16 (0<<7) | btype FP16 (0<<10)
//                          | (N/8)<<17 | (M/16)<<24, K-major both sides
#define IDESC_FP16 0x08200010u

// Arch-specific ('a') feature gate: tcgen05 only exists in the sm_103a SASS pass.
#if defined(__CUDA_ARCH__) && (defined(__CUDA_ARCH_FEAT_SM103_ALL) || defined(__CUDA_ARCH_FEAT_SM100_ALL) || defined(__CUDA_ARCH_FEAT_SM101_ALL) || defined(__CUDA_ARCH_FEAT_SM110_ALL))
#define TC_OK 1
#else
#define TC_OK 0
#endif

// ---------------- scratch (static device globals; no allocation) ----------------
// packed 2-level fp16 images: [b][rowblk(8)][kb(64)] -> 32KB block {h,m} of
// 128 rows x 64 fp16, each 16KB SW128-swizzled
__device__ uint32_t       g_pack[(size_t)BATCH * 8 * NKB * 8192];   // 134 MB
__device__ float          g_S[(size_t)BATCH * M2 * M2];             // 32 MB  S = P P^T
__device__ float          g_w[(size_t)BATCH * CCH * CCH];
__device__ unsigned short g_idx[(size_t)BATCH * CCH * CCH];
__device__ int            g_cnt[BATCH * CCH];

// ======================= helpers =======================
__device__ __forceinline__ uint32_t smem_u32(const void* p) {
    uint32_t a;
    asm("{ .reg .u64 t; cvta.to.shared.u64 t, %1; cvt.u32.u64 %0, t; }" : "=r"(a) : "l"(p));
    return a;
}

// 2-level fp16 split of a pair of fp32 -> packed fp16x2 words (elem0 in low half)
__device__ __forceinline__ void cvt2p(float e0, float e1, uint32_t& hw, uint32_t& mw) {
    asm("cvt.rn.f16x2.f32 %0, %1, %2;" : "=r"(hw) : "f"(e1), "f"(e0));
    const __half2 hp = *reinterpret_cast<const __half2*>(&hw);
    const float2 hf = __half22float2(hp);
    const float r0 = e0 - hf.x, r1 = e1 - hf.y;
    asm("cvt.rn.f16x2.f32 %0, %1, %2;" : "=r"(mw) : "f"(r1), "f"(r0));
}

// =======================================================================
// Kernel 0: split fp32 -> 2 fp16 levels (h, m), written pre-tiled and
// pre-SW128-swizzled into contiguous 32KB {h,m} blocks per (rowblk, kb).
// Each thread: 8 consecutive elements -> 2 x 16B swizzled stores.
// =======================================================================
__global__ __launch_bounds__(256) void split_kernel(const float* __restrict__ x) {
    const size_t idx = (size_t)blockIdx.x * 256 + threadIdx.x;   // 8*1024*512 groups
    const int b   = (int)(idx >> 19);
    const int row = (int)((idx >> 9) & 1023);
    const int k8  = (int)(idx & 511);                            // group of 8 elems

    size_t src;
    if (row < CCH) src = ((size_t)b * CCH + row) * KDIM + (size_t)k8 * 8;
    else           src = ((size_t)(BATCH + b) * CCH + (row - CCH)) * KDIM + (size_t)k8 * 8;

    const float4 v0 = *(const float4*)(x + src);
    const float4 v1 = *(const float4*)(x + src + 4);

    uint4 hv, mv;
    cvt2p(v0.x, v0.y, hv.x, mv.x);
    cvt2p(v0.z, v0.w, hv.y, mv.y);
    cvt2p(v1.x, v1.y, hv.z, mv.z);
    cvt2p(v1.z, v1.w, hv.w, mv.w);

    const int rb = row >> 7, r = row & 127;
    const int kb = k8 >> 3;                               // 64 kbs of 64 elems
    const uint32_t byte_off = (uint32_t)r * 128u + (uint32_t)(k8 & 7) * 16u;
    const uint32_t sw = byte_off ^ ((byte_off >> 3) & 0x70u);
    char* base = (char*)g_pack + ((((size_t)b * 8 + rb) * NKB) + kb) * (size_t)OPER_BYTES + sw;

    *(uint4*)(base)             = hv;
    *(uint4*)(base + IMG_BYTES) = mv;
}

// =======================================================================
// Kernel A: tcgen05 fp16 4-term SYRK, 128x128 tile per CTA, 128 threads.
//   thread 0  : bulk-copy producer (one 32KB block per operand per stage)
//   thread 32 : MMA issuer (16 dispatches/stage: hh, hm, mh, mm)
//   warps 0-3 : TMEM epilogue, mirror via smem transpose
// =======================================================================
#if TC_OK
__device__ __forceinline__ void mbar_init(uint32_t a, uint32_t cnt) {
    asm volatile("mbarrier.init.shared.b64 [%0], %1;" :: "r"(a), "r"(cnt) : "memory");
}
__device__ __forceinline__ void mbar_inval(uint32_t a) {
    asm volatile("mbarrier.inval.shared.b64 [%0];" :: "r"(a) : "memory");
}
__device__ __forceinline__ void mbar_expect_tx(uint32_t a, uint32_t bytes) {
    asm volatile("mbarrier.arrive.expect_tx.shared.b64 _, [%0], %1;" :: "r"(a), "r"(bytes) : "memory");
}
__device__ __forceinline__ void mbar_wait(uint32_t a, uint32_t parity) {
    asm volatile(
        "{\n\t.reg .pred P;\n\t"
        "W%=:\n\t"
        "mbarrier.try_wait.parity.acquire.cta.shared::cta.b64 P, [%0], %1, 0x989680;\n\t"
        "@P bra.uni D%=;\n\t"
        "bra.uni W%=;\n\t"
        "D%=:\n\t}"
        :: "r"(a), "r"(parity) : "memory");
}
__device__ __forceinline__ void bulk_g2s(uint32_t dst, const void* src, uint32_t bytes, uint32_t mbar) {
    asm volatile(
        "cp.async.bulk.shared::cta.global.mbarrier::complete_tx::bytes [%0], [%1], %2, [%3];"
        :: "r"(dst), "l"(src), "r"(bytes), "r"(mbar) : "memory");
}
__device__ __forceinline__ uint64_t make_desc_sw128(uint32_t addr) {
    return ((uint64_t)2 << 61) | ((uint64_t)1 << 46) | ((uint64_t)64 << 32) |
           ((uint64_t)1 << 16) | (((uint64_t)(addr >> 4)) & 0x3FFF);
}
__device__ __forceinline__ void mma_f16_ss(uint32_t d, uint64_t ad, uint64_t bd, uint32_t en) {
    asm volatile(
        "{\n\t.reg .pred p;\n\t"
        "setp.ne.u32 p, %4, 0;\n\t"
        "tcgen05.mma.cta_group::1.kind::f16 [%0], %1, %2, %3, {%5,%5,%5,%5}, p;\n\t}"
        :: "r"(d), "l"(ad), "l"(bd), "r"(IDESC_FP16), "r"(en), "r"(0u) : "memory");
}
__device__ __forceinline__ void tc_commit(uint32_t mbar) {
    asm volatile(
        "tcgen05.commit.cta_group::1.mbarrier::arrive::one.shared::cluster.b64 [%0];"
        :: "r"(mbar) : "memory");
}
#endif

__global__ __launch_bounds__(128, 1) void syrk_tc_kernel() {
#if TC_OK
    extern __shared__ char smem[];
    const uint32_t sb = smem_u32(smem);
    const uint32_t tb = (sb + 1023u) & ~1023u;            // 1024-aligned tile base
    const uint32_t ctl = tb + NSTAGES * STAGE_BYTES;      // control area
    const uint32_t mb_full  = ctl + 16;                   // 3 x 8B
    const uint32_t mb_empty = ctl + 16 + 24;              // 3 x 8B
    const uint32_t mb_done  = ctl + 16 + 48;

    const int tid = threadIdx.x;
    const int wid = tid >> 5, lid = tid & 31;

    const int b = blockIdx.y;
    int ti = 0, rem = blockIdx.x;
    while (rem >= NTILES - ti) { rem -= NTILES - ti; ti++; }
    const int tj = ti + rem;
    const bool diag = (ti == tj);

    if (wid == 0) {
        asm volatile("tcgen05.alloc.cta_group::1.sync.aligned.shared::cta.b32 [%0], %1;"
                     :: "r"(ctl), "r"(128u) : "memory");
    }
    if (tid == 0) {
        for (int s = 0; s < NSTAGES; s++) { mbar_init(mb_full + s * 8, 1); mbar_init(mb_empty + s * 8, 1); }
        mbar_init(mb_done, 1);
        asm volatile("fence.proxy.async.shared::cta;" ::: "memory");
    }
    __syncthreads();

    uint32_t tmem;
    asm volatile("ld.shared.b32 %0, [%1];" : "=r"(tmem) : "r"(ctl));

    const uint32_t txbytes = diag ? OPER_BYTES : (2 * OPER_BYTES);

    if (tid == 0) {
        // ---------------- producer: one 32KB block per operand ----------------
        const char* tiA = (const char*)g_pack + (((size_t)b * 8 + ti) * NKB) * (size_t)OPER_BYTES;
        const char* tiB = (const char*)g_pack + (((size_t)b * 8 + tj) * NKB) * (size_t)OPER_BYTES;
        int ph[NSTAGES] = {0, 0, 0};
        for (int kb = 0; kb < NKB; kb++) {
            const int s = kb % NSTAGES;
            if (kb >= NSTAGES) { mbar_wait(mb_empty + s * 8, ph[s]); ph[s] ^= 1; }
            const uint32_t st = tb + s * STAGE_BYTES;
            const uint32_t fb = mb_full + s * 8;
            mbar_expect_tx(fb, txbytes);
            bulk_g2s(st, tiA + (size_t)kb * OPER_BYTES, OPER_BYTES, fb);
            if (!diag)
                bulk_g2s(st + OPER_BYTES, tiB + (size_t)kb * OPER_BYTES, OPER_BYTES, fb);
        }
    } else if (tid == 32) {
        // ---------------- MMA issuer ----------------
        int ph[NSTAGES] = {0, 0, 0};
        uint32_t en = 0;
        for (int kb = 0; kb < NKB; kb++) {
            const int s = kb % NSTAGES;
            mbar_wait(mb_full + s * 8, ph[s]); ph[s] ^= 1;
            const uint32_t st = tb + s * STAGE_BYTES;
            const uint64_t dAh = make_desc_sw128(st);
            const uint64_t dAm = make_desc_sw128(st + IMG_BYTES);
            const uint64_t dBh = diag ? dAh : make_desc_sw128(st + OPER_BYTES);
            const uint64_t dBm = diag ? dAm : make_desc_sw128(st + OPER_BYTES + IMG_BYTES);
            #pragma unroll
            for (int k = 0; k < 4; k++) {    // 4 k-steps of 16 fp16 (32B = +2 units)
                const uint64_t o = k * 2;
                mma_f16_ss(tmem, dAh + o, dBh + o, en); en = 1;
                mma_f16_ss(tmem, dAh + o, dBm + o, 1);
                mma_f16_ss(tmem, dAm + o, dBh + o, 1);
                mma_f16_ss(tmem, dAm + o, dBm + o, 1);
            }
            tc_commit(mb_empty + s * 8);
        }
        tc_commit(mb_done);
    }

    // ---------------- epilogue ----------------
    mbar_wait(mb_done, 0);
    asm volatile("tcgen05.fence::after_thread_sync;" ::: "memory");

    const size_t Sb = (size_t)b * M2 * M2;
    const int r0 = ti * 128, c0 = tj * 128;
    const int row = r0 + wid * 32 + lid;
    float* trsp = (float*)(smem + (tb - sb));            // reuse stage buffers (32x132 floats)

    for (int cb = 0; cb < 4; cb++) {
        uint32_t d[32];
        asm volatile(
            "tcgen05.ld.sync.aligned.32x32b.x32.b32 "
            "{%0,%1,%2,%3,%4,%5,%6,%7,%8,%9,%10,%11,%12,%13,%14,%15,"
            "%16,%17,%18,%19,%20,%21,%22,%23,%24,%25,%26,%27,%28,%29,%30,%31}, [%32];"
            : "=r"(d[0]), "=r"(d[1]), "=r"(d[2]), "=r"(d[3]), "=r"(d[4]), "=r"(d[5]), "=r"(d[6]), "=r"(d[7]),
              "=r"(d[8]), "=r"(d[9]), "=r"(d[10]), "=r"(d[11]), "=r"(d[12]), "=r"(d[13]), "=r"(d[14]), "=r"(d[15]),
              "=r"(d[16]), "=r"(d[17]), "=r"(d[18]), "=r"(d[19]), "=r"(d[20]), "=r"(d[21]), "=r"(d[22]), "=r"(d[23]),
              "=r"(d[24]), "=r"(d[25]), "=r"(d[26]), "=r"(d[27]), "=r"(d[28]), "=r"(d[29]), "=r"(d[30]), "=r"(d[31])
            : "r"(tmem + cb * 32));
        asm volatile("tcgen05.wait::ld.sync.aligned;" ::: "memory");

        float* dst = g_S + Sb + (size_t)row * M2 + c0 + cb * 32;
        #pragma unroll
        for (int q = 0; q < 8; q++) {
            float4 v = make_float4(__uint_as_float(d[q * 4 + 0]), __uint_as_float(d[q * 4 + 1]),
                                   __uint_as_float(d[q * 4 + 2]), __uint_as_float(d[q * 4 + 3]));
            *(float4*)(dst + q * 4) = v;
        }

        if (!diag) {
            // transpose 128x32 -> 32x128 via smem, then coalesced STG
            const int lr = wid * 32 + lid;       // local row 0..127
            #pragma unroll
            for (int j = 0; j < 32; j++)
                trsp[j * 132 + lr] = __uint_as_float(d[j]);
            __syncthreads();
            const int mj = tid >> 2;             // mirror row 0..31 (local)
            const int ch = tid & 3;              // 32-col chunk
            float* mdst = g_S + Sb + (size_t)(c0 + cb * 32 + mj) * M2 + r0 + ch * 32;
            const float* msrc = trsp + mj * 132 + ch * 32;
            #pragma unroll
            for (int q = 0; q < 8; q++)
                *(float4*)(mdst + q * 4) = *(const float4*)(msrc + q * 4);
            __syncthreads();
        }
    }

    __syncthreads();
    if (tid == 0) {
        for (int s = 0; s < NSTAGES; s++) { mbar_inval(mb_full + s * 8); mbar_inval(mb_empty + s * 8); }
        mbar_inval(mb_done);
    }
    __syncthreads();
    if (wid == 0) {
        asm volatile("tcgen05.dealloc.cta_group::1.sync.aligned.b32 %0, %1;" :: "r"(tmem), "r"(128u));
    }
#endif
}

// =======================================================================
// Kernel B: softmax of (max-er)^2+(max-ei)^2 over S rows + compaction
// =======================================================================
__device__ __forceinline__ float blkReduce(float v, float* red, bool isMax) {
    #pragma unroll
    for (int o = 16; o > 0; o >>= 1) {
        float tv = __shfl_xor_sync(0xffffffffu, v, o);
        v = isMax ? fmaxf(v, tv) : (v + tv);
    }
    const int lane = threadIdx.x & 31, wid = threadIdx.x >> 5;
    if (lane == 0) red[wid] = v;
    __syncthreads();
    if (wid == 0) {
        float tv = (lane < 16) ? red[lane] : (isMax ? -3.4e38f : 0.0f);
        #pragma unroll
        for (int o = 8; o > 0; o >>= 1) {
            float u = __shfl_xor_sync(0xffffffffu, tv, o);
            tv = isMax ? fmaxf(tv, u) : (tv + u);
        }
        if (lane == 0) red[0] = tv;
    }
    __syncthreads();
    const float res = red[0];
    __syncthreads();
    return res;
}

__global__ void attn_kernel() {
    __shared__ float red[16];
    __shared__ int wcnt[16];
    __shared__ int woff[16];

    const int r = blockIdx.x;
    const int b = r >> 9, c = r & 511;
    const int d = threadIdx.x;
    const int lane = d & 31, wid = d >> 5;

    const float* S0 = g_S + ((size_t)b * M2 + c) * M2;
    const float* S1 = g_S + ((size_t)b * M2 + CCH + c) * M2;

    const float er = S0[d] - S1[CCH + d];
    const float ei = S0[CCH + d] + S1[d];

    const float mer = blkReduce(er, red, true);
    const float mei = blkReduce(ei, red, true);

    const float ar = mer - er;
    const float ai = mei - ei;
    const float s = ar * ar + ai * ai;

    const float smax = blkReduce(s, red, true);
    const float e = expf(s - smax);
    const float Z = blkReduce(e, red, false);
    const float w = e / Z;

    const bool keep = w > 1e-10f;
    const unsigned msk = __ballot_sync(0xffffffffu, keep);
    const int inpos = __popc(msk & ((1u << lane) - 1u));
    if (lane == 0) wcnt[wid] = __popc(msk);
    __syncthreads();
    if (d == 0) {
        int run = 0;
        #pragma unroll
        for (int i = 0; i < 16; i++) { woff[i] = run; run += wcnt[i]; }
        g_cnt[r] = run;
    }
    __syncthreads();
    if (keep) {
        const int pos = woff[wid] + inpos;
        g_idx[(size_t)r * CCH + pos] = (unsigned short)d;
        g_w[(size_t)r * CCH + pos] = w;
    }
}

// =======================================================================
// Kernel C: out = gamma * (sparse attention @ q) + x   (R6 version)
// =======================================================================
__global__ __launch_bounds__(256) void apply_kernel(const float* __restrict__ x,
                                                    const float* __restrict__ gamma,
                                                    float* __restrict__ out) {
    const int r = blockIdx.x;
    const int b = r >> 9, c = r & 511;
    const int n = blockIdx.y * 1024 + threadIdx.x * 4;

    const int cnt = g_cnt[r];
    const float g = gamma[0];
    const size_t imagOff = (size_t)BATCH * CCH * KDIM;
    const float* xr = x;
    const float* xi = x + imagOff;

    float4 ar = make_float4(0.f, 0.f, 0.f, 0.f);
    float4 ai = make_float4(0.f, 0.f, 0.f, 0.f);
    const size_t lbase = (size_t)r * CCH;

    for (int i = 0; i < cnt; i++) {
        const int dch = g_idx[lbase + i];
        const float w = g_w[lbase + i];
        const size_t q = ((size_t)b * CCH + dch) * KDIM + n;
        const float4 qr = *(const float4*)(xr + q);
        const float4 qi = *(const float4*)(xi + q);
        ar.x += w * qr.x; ar.y += w * qr.y; ar.z += w * qr.z; ar.w += w * qr.w;
        ai.x += w * qi.x; ai.y += w * qi.y; ai.z += w * qi.z; ai.w += w * qi.w;
    }

    const size_t o = ((size_t)b * CCH + c) * KDIM + n;
    const float4 xrv = *(const float4*)(xr + o);
    const float4 xiv = *(const float4*)(xi + o);
    float4 orr = make_float4(g * ar.x + xrv.x, g * ar.y + xrv.y,
                             g * ar.z + xrv.z, g * ar.w + xrv.w);
    float4 oii = make_float4(g * ai.x + xiv.x, g * ai.y + xiv.y,
                             g * ai.z + xiv.z, g * ai.w + xiv.w);
    *(float4*)(out + o) = orr;
    *(float4*)(out + imagOff + o) = oii;
}

// =======================================================================
extern "C" void kernel_launch(void* const* d_in, const int* in_sizes, int n_in,
                              void* d_out, int out_size) {
    const float* x = (const float*)d_in[0];
    const float* gamma = (const float*)d_in[1];
    float* out = (float*)d_out;

    const int SMEM_DYN = 1024 + NSTAGES * STAGE_BYTES + 256;   // ~193.5 KB
    cudaFuncSetAttribute(syrk_tc_kernel, cudaFuncAttributeMaxDynamicSharedMemorySize, SMEM_DYN);

    split_kernel<<<(BATCH * 1024 * 512) / 256, 256>>>(x);
    syrk_tc_kernel<<<dim3(NTILES * (NTILES + 1) / 2, BATCH), 128, SMEM_DYN>>>();
    attn_kernel<<<BATCH * CCH, 512>>>();
    apply_kernel<<<dim3(BATCH * CCH, 4), 256>>>(x, gamma, out);
}